// round 7
// baseline (speedup 1.0000x reference)
#include <cuda_runtime.h>
#include <math.h>
#include <stdint.h>

#define BATCH   16
#define LSEQ    2048
#define DMODEL  256
#define DINNER  512
#define DSTATE  16
#define NOUT    256
#define NROWS   (BATCH*LSEQ)   /* 32768 */

// ---------------- device scratch (no allocations allowed) ----------------
__device__ float  g_xz[(size_t)NROWS * 1024];        // in_proj output (x | silu(z))
__device__ float4 g_scanin[(size_t)NROWS * DINNER];  // (delta, delta*xc, silu(z), xc*D)
__device__ float2 g_bc[(size_t)NROWS * DSTATE];      // (B_n, C_n) interleaved
__device__ float  g_y[(size_t)NROWS * DINNER];       // scan output (pre out_proj)
__device__ float  g_t1[(size_t)NROWS * NOUT];        // silu(out_proj)
__device__ float  g_psum[512 * 2];                   // per-block (sum, sumsq)
__device__ float2 g_stats[BATCH];                    // (mean, rstd)

__device__ __forceinline__ float silu_f(float v) {
    return v / (1.f + __expf(-v));
}

// ---------------------------- bf16 helpers --------------------------------
__device__ __forceinline__ uint32_t pack_bf16x2(float hi, float lo) {
    uint32_t r;
    asm("cvt.rn.bf16x2.f32 %0, %1, %2;" : "=r"(r) : "f"(hi), "f"(lo));
    return r;
}
__device__ __forceinline__ float lo_f32(uint32_t p) {
    return __uint_as_float(p << 16);
}
__device__ __forceinline__ float hi_f32(uint32_t p) {
    return __uint_as_float(p & 0xffff0000u);
}
__device__ __forceinline__ void mma_bf16(float* c, const uint32_t* a,
                                         const uint32_t* b) {
    asm volatile(
        "mma.sync.aligned.m16n8k16.row.col.f32.bf16.bf16.f32 "
        "{%0,%1,%2,%3}, {%4,%5,%6,%7}, {%8,%9}, {%0,%1,%2,%3};"
        : "+f"(c[0]), "+f"(c[1]), "+f"(c[2]), "+f"(c[3])
        : "r"(a[0]), "r"(a[1]), "r"(a[2]), "r"(a[3]), "r"(b[0]), "r"(b[1]));
}

// -------------------- 3x-bf16 tensor-core NT GEMM -------------------------
// (unchanged from round 6: 1096us best, gemm<1> 97.7us)
#define KSTR 264
template <int EPI>
__global__ void __launch_bounds__(256, 2)
gemm_bf16_kernel(const float* __restrict__ A, const float* __restrict__ B,
                 float* __restrict__ C, int N, int K,
                 const float* __restrict__ bias)
{
    __shared__ uint32_t Ah[4][KSTR], Al[4][KSTR];
    __shared__ uint32_t Bh[4][KSTR], Bl[4][KSTR];
    __shared__ float red_s[256], red_ss[256];

    const int tid = threadIdx.x;
    const int wid = tid >> 5;
    const int lane = tid & 31;
    const int grp = lane >> 2;       // 0..7
    const int tg  = lane & 3;        // 0..3
    const int warp_m = wid & 1;      // 2 x 64 rows
    const int warp_n = wid >> 1;     // 4 x 32 cols
    const int bm = blockIdx.y, bn = blockIdx.x;

    const int lrow = tid >> 2;       // 0..63
    const int lkq  = tid & 3;        // k-quad (4 floats each)

    const int k2a = lkq * 2, k2b = lkq * 2 + 1;
    const int sa_row = k2a & 3, sa_kh = k2a >> 2;
    const int sb_row = k2b & 3, sb_kh = k2b >> 2;

    float acc[4][4][4] = {};

    const int nkt = K >> 4;
    for (int kt = 0; kt < nkt; ++kt) {
        __syncthreads();
#pragma unroll
        for (int rr = 0; rr < 2; ++rr) {
            const int r = lrow + rr * 64;
            float4 va = *(const float4*)(A + (size_t)(bm * 128 + r) * K +
                                         kt * 16 + lkq * 4);
            float4 vb = *(const float4*)(B + (size_t)(bn * 128 + r) * K +
                                         kt * 16 + lkq * 4);
            uint32_t h01 = pack_bf16x2(va.y, va.x);
            uint32_t h23 = pack_bf16x2(va.w, va.z);
            uint32_t l01 = pack_bf16x2(va.y - hi_f32(h01), va.x - lo_f32(h01));
            uint32_t l23 = pack_bf16x2(va.w - hi_f32(h23), va.z - lo_f32(h23));
            Ah[sa_row][r * 2 + sa_kh] = h01;
            Al[sa_row][r * 2 + sa_kh] = l01;
            Ah[sb_row][r * 2 + sb_kh] = h23;
            Al[sb_row][r * 2 + sb_kh] = l23;
            h01 = pack_bf16x2(vb.y, vb.x);
            h23 = pack_bf16x2(vb.w, vb.z);
            l01 = pack_bf16x2(vb.y - hi_f32(h01), vb.x - lo_f32(h01));
            l23 = pack_bf16x2(vb.w - hi_f32(h23), vb.z - lo_f32(h23));
            Bh[sa_row][r * 2 + sa_kh] = h01;
            Bl[sa_row][r * 2 + sa_kh] = l01;
            Bh[sb_row][r * 2 + sb_kh] = h23;
            Bl[sb_row][r * 2 + sb_kh] = l23;
        }
        __syncthreads();

        uint2 af[4][2], bh[4], bl[4];
#pragma unroll
        for (int mi = 0; mi < 4; ++mi) {
            const int m = warp_m * 64 + mi * 16 + grp;
            af[mi][0] = *(const uint2*)&Ah[tg][2 * m];
            af[mi][1] = *(const uint2*)&Ah[tg][2 * (m + 8)];
        }
#pragma unroll
        for (int ni = 0; ni < 4; ++ni) {
            const int n = warp_n * 32 + ni * 8 + grp;
            bh[ni] = *(const uint2*)&Bh[tg][2 * n];
            bl[ni] = *(const uint2*)&Bl[tg][2 * n];
        }
#pragma unroll
        for (int mi = 0; mi < 4; ++mi) {
            const uint32_t a[4] = {af[mi][0].x, af[mi][1].x,
                                   af[mi][0].y, af[mi][1].y};
#pragma unroll
            for (int ni = 0; ni < 4; ++ni) {
                const uint32_t b0[2] = {bh[ni].x, bh[ni].y};
                const uint32_t b1[2] = {bl[ni].x, bl[ni].y};
                mma_bf16(acc[mi][ni], a, b0);
                mma_bf16(acc[mi][ni], a, b1);
            }
        }
#pragma unroll
        for (int mi = 0; mi < 4; ++mi) {
            const int m = warp_m * 64 + mi * 16 + grp;
            af[mi][0] = *(const uint2*)&Al[tg][2 * m];
            af[mi][1] = *(const uint2*)&Al[tg][2 * (m + 8)];
        }
#pragma unroll
        for (int mi = 0; mi < 4; ++mi) {
            const uint32_t a[4] = {af[mi][0].x, af[mi][1].x,
                                   af[mi][0].y, af[mi][1].y};
#pragma unroll
            for (int ni = 0; ni < 4; ++ni) {
                const uint32_t b0[2] = {bh[ni].x, bh[ni].y};
                mma_bf16(acc[mi][ni], a, b0);
            }
        }
    }

    float s = 0.f, ss = 0.f;
    const bool dos = (EPI == 1) || (EPI == 3 && bn >= 4);
#pragma unroll
    for (int mi = 0; mi < 4; ++mi) {
        const int row0 = bm * 128 + warp_m * 64 + mi * 16 + grp;
#pragma unroll
        for (int ni = 0; ni < 4; ++ni) {
            const int col = bn * 128 + warp_n * 32 + ni * 8 + tg * 2;
            float v0 = acc[mi][ni][0], v1 = acc[mi][ni][1];
            float v2 = acc[mi][ni][2], v3 = acc[mi][ni][3];
            if (dos) { v0 = silu_f(v0); v1 = silu_f(v1);
                       v2 = silu_f(v2); v3 = silu_f(v3); }
            if (EPI == 2) {
                const float b0 = bias[col], b1 = bias[col + 1];
                v0 += b0; v1 += b1; v2 += b0; v3 += b1;
                s += v0 + v1 + v2 + v3;
                ss += v0 * v0 + v1 * v1 + v2 * v2 + v3 * v3;
            }
            *(float2*)(C + (size_t)row0 * N + col)       = make_float2(v0, v1);
            *(float2*)(C + (size_t)(row0 + 8) * N + col) = make_float2(v2, v3);
        }
    }

    if (EPI == 2) {
        red_s[tid] = s; red_ss[tid] = ss;
        __syncthreads();
        for (int off = 128; off > 0; off >>= 1) {
            if (tid < off) { red_s[tid] += red_s[tid + off];
                             red_ss[tid] += red_ss[tid + off]; }
            __syncthreads();
        }
        if (tid == 0) {
            int pid = bm * gridDim.x + bn;
            g_psum[2 * pid] = red_s[0];
            g_psum[2 * pid + 1] = red_ss[0];
        }
    }
}

// ---------- fused causal conv + SiLU + x_proj + dt_proj + pack -----------
#define TOK 16
__global__ void __launch_bounds__(512)
convproj_kernel(const float* __restrict__ conv_w, const float* __restrict__ conv_b,
                const float* __restrict__ x_proj_w, const float* __restrict__ dt_proj_w,
                const float* __restrict__ dt_proj_b, const float* __restrict__ D_skip)
{
    const int b  = blockIdx.x >> 7;
    const int l0 = (blockIdx.x & 127) * TOK;
    const int d  = threadIdx.x;

    __shared__ float xc_s[TOK][512];
    __shared__ float xdbl_s[TOK][48];

    {
        float4 cw = ((const float4*)conv_w)[d];
        float cb = conv_b[d];
        const float* xcol = g_xz + (size_t)(b * 2048 + l0) * 1024 + d;
        float w0 = (l0 - 3 >= 0) ? xcol[-3 * 1024] : 0.f;
        float w1 = (l0 - 2 >= 0) ? xcol[-2 * 1024] : 0.f;
        float w2 = (l0 - 1 >= 0) ? xcol[-1 * 1024] : 0.f;
#pragma unroll
        for (int t = 0; t < TOK; ++t) {
            float cur = xcol[t * 1024];
            float acc = cb;
            acc = fmaf(w0, cw.x, acc);
            acc = fmaf(w1, cw.y, acc);
            acc = fmaf(w2, cw.z, acc);
            acc = fmaf(cur, cw.w, acc);
            xc_s[t][d] = silu_f(acc);
            w0 = w1; w1 = w2; w2 = cur;
        }
    }
    __syncthreads();

    {
        const int warp = d >> 5, lane = d & 31;
        float4 wv[3][4];
        const float4* xw4 = (const float4*)x_proj_w;
#pragma unroll
        for (int jj = 0; jj < 3; ++jj) {
            const float4* wrow = xw4 + (size_t)(warp * 3 + jj) * 128;
#pragma unroll
            for (int q = 0; q < 4; ++q)
                wv[jj][q] = wrow[lane + q * 32];
        }
#pragma unroll
        for (int t = 0; t < TOK; ++t) {
            float4 xv[4];
            const float4* xr = (const float4*)&xc_s[t][0];
#pragma unroll
            for (int q = 0; q < 4; ++q) xv[q] = xr[lane + q * 32];
            float a0 = 0.f, a1 = 0.f, a2 = 0.f;
#pragma unroll
            for (int q = 0; q < 4; ++q) {
                a0 = fmaf(xv[q].x, wv[0][q].x, a0); a0 = fmaf(xv[q].y, wv[0][q].y, a0);
                a0 = fmaf(xv[q].z, wv[0][q].z, a0); a0 = fmaf(xv[q].w, wv[0][q].w, a0);
                a1 = fmaf(xv[q].x, wv[1][q].x, a1); a1 = fmaf(xv[q].y, wv[1][q].y, a1);
                a1 = fmaf(xv[q].z, wv[1][q].z, a1); a1 = fmaf(xv[q].w, wv[1][q].w, a1);
                a2 = fmaf(xv[q].x, wv[2][q].x, a2); a2 = fmaf(xv[q].y, wv[2][q].y, a2);
                a2 = fmaf(xv[q].z, wv[2][q].z, a2); a2 = fmaf(xv[q].w, wv[2][q].w, a2);
            }
#pragma unroll
            for (int off = 16; off; off >>= 1) {
                a0 += __shfl_xor_sync(0xffffffffu, a0, off);
                a1 += __shfl_xor_sync(0xffffffffu, a1, off);
                a2 += __shfl_xor_sync(0xffffffffu, a2, off);
            }
            if (lane == 0) {
                xdbl_s[t][warp * 3 + 0] = a0;
                xdbl_s[t][warp * 3 + 1] = a1;
                xdbl_s[t][warp * 3 + 2] = a2;
            }
        }
    }
    __syncthreads();

    {
        const float4* dw = (const float4*)(dt_proj_w + d * 16);
        float4 dw0 = dw[0], dw1 = dw[1], dw2 = dw[2], dw3 = dw[3];
        const float dtb = dt_proj_b[d];
        const float Dv = D_skip[d];
        const float* zptr = g_xz + (size_t)(b * 2048 + l0) * 1024 + 512 + d;
        float4* outp = g_scanin + (size_t)(b * 2048 + l0) * 512 + d;
#pragma unroll
        for (int t = 0; t < TOK; ++t) {
            const float4* xr = (const float4*)&xdbl_s[t][0];
            float4 x0 = xr[0], x1 = xr[1], x2 = xr[2], x3 = xr[3];
            float dt = dtb;
            dt = fmaf(x0.x, dw0.x, dt); dt = fmaf(x0.y, dw0.y, dt);
            dt = fmaf(x0.z, dw0.z, dt); dt = fmaf(x0.w, dw0.w, dt);
            dt = fmaf(x1.x, dw1.x, dt); dt = fmaf(x1.y, dw1.y, dt);
            dt = fmaf(x1.z, dw1.z, dt); dt = fmaf(x1.w, dw1.w, dt);
            dt = fmaf(x2.x, dw2.x, dt); dt = fmaf(x2.y, dw2.y, dt);
            dt = fmaf(x2.z, dw2.z, dt); dt = fmaf(x2.w, dw2.w, dt);
            dt = fmaf(x3.x, dw3.x, dt); dt = fmaf(x3.y, dw3.y, dt);
            dt = fmaf(x3.z, dw3.z, dt); dt = fmaf(x3.w, dw3.w, dt);
            float delta = (dt > 20.f) ? dt : __logf(1.f + __expf(dt));
            float xc = xc_s[t][d];
            float sz = zptr[(size_t)t * 1024];
            outp[(size_t)t * 512] = make_float4(delta, delta * xc, sz, xc * Dv);
        }
    }

    if (d < TOK * DSTATE) {
        const int t = d >> 4, n = d & 15;
        g_bc[(size_t)(b * 2048 + l0 + t) * 16 + n] =
            make_float2(xdbl_s[t][16 + n], xdbl_s[t][32 + n]);
    }
}

// ---------------------- diagonal selective scan (v4) -----------------------
// 4096 warps: warp = 2 channels x 16 lanes x 1 state/lane.
// Explicit double-buffered SB=4 prefetch keeps loads in flight during compute.
#define SB 4
__global__ void __launch_bounds__(128, 6)
scan_kernel(const float* __restrict__ A_log)
{
    const int w = blockIdx.x * 4 + (threadIdx.x >> 5);  // 0..4095
    const int b = w >> 8;                               // 16 batches
    const int dpair = (w & 255) * 2;
    const int lane = threadIdx.x & 31;
    const int half = lane >> 4;
    const int n = lane & 15;
    const int d = dpair + half;

    const float LOG2E = 1.44269504f;
    const float An = -__expf(A_log[d * 16 + n]) * LOG2E;

    const float4* vp = g_scanin + (size_t)(b * 2048) * 512 + d;
    const float2* bp = g_bc + (size_t)(b * 2048) * 16 + n;
    float* yp = g_y + (size_t)(b * 2048) * 512 + d;

    float h = 0.f;
    float4 vbuf[2][SB];
    float2 bbuf[2][SB];
#pragma unroll
    for (int j = 0; j < SB; ++j) {
        vbuf[0][j] = vp[(size_t)j * 512];
        bbuf[0][j] = bp[(size_t)j * 16];
    }
    for (int tb = 0; tb < 2048; tb += SB) {
        const int cur = (tb >> 2) & 1, nxt = cur ^ 1;
        if (tb + SB < 2048) {
#pragma unroll
            for (int j = 0; j < SB; ++j) {
                vbuf[nxt][j] = vp[(size_t)(tb + SB + j) * 512];
                bbuf[nxt][j] = bp[(size_t)(tb + SB + j) * 16];
            }
        }
#pragma unroll
        for (int j = 0; j < SB; ++j) {
            float4 v  = vbuf[cur][j];   // (delta, delta*xc, silu(z), xc*D)
            float2 bc = bbuf[cur][j];   // (B_n, C_n)
            float dA = exp2f(v.x * An);
            h = fmaf(dA, h, v.y * bc.x);
            float p = h * bc.y;
            p += __shfl_xor_sync(0xffffffffu, p, 1);
            p += __shfl_xor_sync(0xffffffffu, p, 2);
            p += __shfl_xor_sync(0xffffffffu, p, 4);
            p += __shfl_xor_sync(0xffffffffu, p, 8);
            if (n == 0)
                yp[(size_t)(tb + j) * 512] = (p + v.w) * v.z;
        }
    }
}

// ------------------------- LayerNorm stats + apply ------------------------
__global__ void stats_kernel()
{
    int b = threadIdx.x;
    if (b >= BATCH) return;
    double s = 0.0, ss = 0.0;
    for (int bm = b * 16; bm < b * 16 + 16; ++bm)
        for (int bn = 0; bn < 2; ++bn) {
            int pid = bm * 2 + bn;
            s  += (double)g_psum[2 * pid];
            ss += (double)g_psum[2 * pid + 1];
        }
    const double nd = (double)LSEQ * NOUT;
    double mu = s / nd;
    double var = ss / nd - mu * mu;
    g_stats[b] = make_float2((float)mu, (float)rsqrt(var + 1e-5));
}

__global__ void __launch_bounds__(256)
norm_kernel(float* __restrict__ out, const float* __restrict__ lnw,
            const float* __restrict__ lnb)
{
    size_t i4 = (size_t)blockIdx.x * 256 + threadIdx.x;
    size_t base = i4 * 4;
    int row = (int)(base >> 8);
    int b = row >> 11;
    int l = row & 2047;
    int o = (int)(base & 255);
    float2 st = g_stats[b];
    float4 v = *(float4*)(out + base);
    const float4 w  = *(const float4*)(lnw + (size_t)l * 256 + o);
    const float4 bb = *(const float4*)(lnb + (size_t)l * 256 + o);
    v.x = (v.x - st.x) * st.y * w.x + bb.x;
    v.y = (v.y - st.x) * st.y * w.y + bb.y;
    v.z = (v.z - st.x) * st.y * w.z + bb.z;
    v.w = (v.w - st.x) * st.y * w.w + bb.w;
    *(float4*)(out + base) = v;
}

// ------------------------------- launch -----------------------------------
extern "C" void kernel_launch(void* const* d_in, const int* in_sizes, int n_in,
                              void* d_out, int out_size)
{
    const float* inputs    = (const float*)d_in[0];
    const float* in_proj_w = (const float*)d_in[1];
    const float* conv_w    = (const float*)d_in[2];
    const float* conv_b    = (const float*)d_in[3];
    const float* x_proj_w  = (const float*)d_in[4];
    const float* dt_proj_w = (const float*)d_in[5];
    const float* dt_proj_b = (const float*)d_in[6];
    const float* A_log     = (const float*)d_in[7];
    const float* D_skip    = (const float*)d_in[8];
    const float* out_proj_w= (const float*)d_in[9];
    const float* dim_w     = (const float*)d_in[10];
    const float* dim_b     = (const float*)d_in[11];
    const float* ln_w      = (const float*)d_in[12];
    const float* ln_b      = (const float*)d_in[13];
    float* out = (float*)d_out;

    float *xz, *y, *t1;
    cudaGetSymbolAddress((void**)&xz, g_xz);
    cudaGetSymbolAddress((void**)&y,  g_y);
    cudaGetSymbolAddress((void**)&t1, g_t1);

    // 1) xz = inputs @ in_proj_w^T  [32768 x 1024], silu on z half (bn>=4)
    gemm_bf16_kernel<3><<<dim3(1024 / 128, NROWS / 128), 256>>>(
        inputs, in_proj_w, xz, 1024, 256, nullptr);

    // 2) conv + silu + x_proj + dt_proj, packed scan inputs
    convproj_kernel<<<NROWS / TOK, 512>>>(conv_w, conv_b, x_proj_w,
                                          dt_proj_w, dt_proj_b, D_skip);

    // 3) selective scan (v4: 4096 warps, pipelined prefetch)
    scan_kernel<<<1024, 128>>>(A_log);

    // 4) t1 = silu(y @ out_proj_w^T)  [32768 x 256]
    gemm_bf16_kernel<1><<<dim3(256 / 128, NROWS / 128), 256>>>(
        y, out_proj_w, t1, 256, 512, nullptr);

    // 5) out = t1 @ dim_w^T + dim_b, + per-block partial sums
    gemm_bf16_kernel<2><<<dim3(256 / 128, NROWS / 128), 256>>>(
        t1, dim_w, out, 256, 256, dim_b);

    // 6) per-batch LayerNorm
    stats_kernel<<<1, 32>>>();
    norm_kernel<<<(NROWS * NOUT / 4) / 256, 256>>>(out, ln_w, ln_b);
}

// round 8
// speedup vs baseline: 2.0404x; 2.0404x over previous
#include <cuda_runtime.h>
#include <math.h>
#include <stdint.h>

#define BATCH   16
#define LSEQ    2048
#define DMODEL  256
#define DINNER  512
#define DSTATE  16
#define NOUT    256
#define NROWS   (BATCH*LSEQ)   /* 32768 */

// ---------------- device scratch (no allocations allowed) ----------------
__device__ float  g_xz[(size_t)NROWS * 1024];        // in_proj output (x | silu(z))
__device__ float4 g_scanin[(size_t)NROWS * DINNER];  // (delta, delta*xc, silu(z), xc*D)
__device__ float2 g_bc[(size_t)NROWS * DSTATE];      // (B_n, C_n) interleaved
__device__ float  g_y[(size_t)NROWS * DINNER];       // scan output (pre out_proj)
__device__ float  g_t1[(size_t)NROWS * NOUT];        // silu(out_proj)
__device__ float  g_psum[512 * 2];                   // per-block (sum, sumsq)
__device__ float2 g_stats[BATCH];                    // (mean, rstd)

__device__ __forceinline__ float silu_f(float v) {
    return v / (1.f + __expf(-v));
}

// ---------------------------- bf16 helpers --------------------------------
__device__ __forceinline__ uint32_t pack_bf16x2(float hi, float lo) {
    uint32_t r;
    asm("cvt.rn.bf16x2.f32 %0, %1, %2;" : "=r"(r) : "f"(hi), "f"(lo));
    return r;
}
__device__ __forceinline__ float lo_f32(uint32_t p) {
    return __uint_as_float(p << 16);
}
__device__ __forceinline__ float hi_f32(uint32_t p) {
    return __uint_as_float(p & 0xffff0000u);
}
__device__ __forceinline__ void mma_bf16(float* c, const uint32_t* a,
                                         const uint32_t* b) {
    asm volatile(
        "mma.sync.aligned.m16n8k16.row.col.f32.bf16.bf16.f32 "
        "{%0,%1,%2,%3}, {%4,%5,%6,%7}, {%8,%9}, {%0,%1,%2,%3};"
        : "+f"(c[0]), "+f"(c[1]), "+f"(c[2]), "+f"(c[3])
        : "r"(a[0]), "r"(a[1]), "r"(a[2]), "r"(a[3]), "r"(b[0]), "r"(b[1]));
}

// -------------------- 3x-bf16 tensor-core NT GEMM -------------------------
// (unchanged from round 6: best kernel, gemm<1> 97.7us)
#define KSTR 264
template <int EPI>
__global__ void __launch_bounds__(256, 2)
gemm_bf16_kernel(const float* __restrict__ A, const float* __restrict__ B,
                 float* __restrict__ C, int N, int K,
                 const float* __restrict__ bias)
{
    __shared__ uint32_t Ah[4][KSTR], Al[4][KSTR];
    __shared__ uint32_t Bh[4][KSTR], Bl[4][KSTR];
    __shared__ float red_s[256], red_ss[256];

    const int tid = threadIdx.x;
    const int wid = tid >> 5;
    const int lane = tid & 31;
    const int grp = lane >> 2;       // 0..7
    const int tg  = lane & 3;        // 0..3
    const int warp_m = wid & 1;      // 2 x 64 rows
    const int warp_n = wid >> 1;     // 4 x 32 cols
    const int bm = blockIdx.y, bn = blockIdx.x;

    const int lrow = tid >> 2;       // 0..63
    const int lkq  = tid & 3;        // k-quad (4 floats each)

    const int k2a = lkq * 2, k2b = lkq * 2 + 1;
    const int sa_row = k2a & 3, sa_kh = k2a >> 2;
    const int sb_row = k2b & 3, sb_kh = k2b >> 2;

    float acc[4][4][4] = {};

    const int nkt = K >> 4;
    for (int kt = 0; kt < nkt; ++kt) {
        __syncthreads();
#pragma unroll
        for (int rr = 0; rr < 2; ++rr) {
            const int r = lrow + rr * 64;
            float4 va = *(const float4*)(A + (size_t)(bm * 128 + r) * K +
                                         kt * 16 + lkq * 4);
            float4 vb = *(const float4*)(B + (size_t)(bn * 128 + r) * K +
                                         kt * 16 + lkq * 4);
            uint32_t h01 = pack_bf16x2(va.y, va.x);
            uint32_t h23 = pack_bf16x2(va.w, va.z);
            uint32_t l01 = pack_bf16x2(va.y - hi_f32(h01), va.x - lo_f32(h01));
            uint32_t l23 = pack_bf16x2(va.w - hi_f32(h23), va.z - lo_f32(h23));
            Ah[sa_row][r * 2 + sa_kh] = h01;
            Al[sa_row][r * 2 + sa_kh] = l01;
            Ah[sb_row][r * 2 + sb_kh] = h23;
            Al[sb_row][r * 2 + sb_kh] = l23;
            h01 = pack_bf16x2(vb.y, vb.x);
            h23 = pack_bf16x2(vb.w, vb.z);
            l01 = pack_bf16x2(vb.y - hi_f32(h01), vb.x - lo_f32(h01));
            l23 = pack_bf16x2(vb.w - hi_f32(h23), vb.z - lo_f32(h23));
            Bh[sa_row][r * 2 + sa_kh] = h01;
            Bl[sa_row][r * 2 + sa_kh] = l01;
            Bh[sb_row][r * 2 + sb_kh] = h23;
            Bl[sb_row][r * 2 + sb_kh] = l23;
        }
        __syncthreads();

        uint2 af[4][2], bh[4], bl[4];
#pragma unroll
        for (int mi = 0; mi < 4; ++mi) {
            const int m = warp_m * 64 + mi * 16 + grp;
            af[mi][0] = *(const uint2*)&Ah[tg][2 * m];
            af[mi][1] = *(const uint2*)&Ah[tg][2 * (m + 8)];
        }
#pragma unroll
        for (int ni = 0; ni < 4; ++ni) {
            const int n = warp_n * 32 + ni * 8 + grp;
            bh[ni] = *(const uint2*)&Bh[tg][2 * n];
            bl[ni] = *(const uint2*)&Bl[tg][2 * n];
        }
#pragma unroll
        for (int mi = 0; mi < 4; ++mi) {
            const uint32_t a[4] = {af[mi][0].x, af[mi][1].x,
                                   af[mi][0].y, af[mi][1].y};
#pragma unroll
            for (int ni = 0; ni < 4; ++ni) {
                const uint32_t b0[2] = {bh[ni].x, bh[ni].y};
                const uint32_t b1[2] = {bl[ni].x, bl[ni].y};
                mma_bf16(acc[mi][ni], a, b0);
                mma_bf16(acc[mi][ni], a, b1);
            }
        }
#pragma unroll
        for (int mi = 0; mi < 4; ++mi) {
            const int m = warp_m * 64 + mi * 16 + grp;
            af[mi][0] = *(const uint2*)&Al[tg][2 * m];
            af[mi][1] = *(const uint2*)&Al[tg][2 * (m + 8)];
        }
#pragma unroll
        for (int mi = 0; mi < 4; ++mi) {
            const uint32_t a[4] = {af[mi][0].x, af[mi][1].x,
                                   af[mi][0].y, af[mi][1].y};
#pragma unroll
            for (int ni = 0; ni < 4; ++ni) {
                const uint32_t b0[2] = {bh[ni].x, bh[ni].y};
                mma_bf16(acc[mi][ni], a, b0);
            }
        }
    }

    float s = 0.f, ss = 0.f;
    const bool dos = (EPI == 1) || (EPI == 3 && bn >= 4);
#pragma unroll
    for (int mi = 0; mi < 4; ++mi) {
        const int row0 = bm * 128 + warp_m * 64 + mi * 16 + grp;
#pragma unroll
        for (int ni = 0; ni < 4; ++ni) {
            const int col = bn * 128 + warp_n * 32 + ni * 8 + tg * 2;
            float v0 = acc[mi][ni][0], v1 = acc[mi][ni][1];
            float v2 = acc[mi][ni][2], v3 = acc[mi][ni][3];
            if (dos) { v0 = silu_f(v0); v1 = silu_f(v1);
                       v2 = silu_f(v2); v3 = silu_f(v3); }
            if (EPI == 2) {
                const float b0 = bias[col], b1 = bias[col + 1];
                v0 += b0; v1 += b1; v2 += b0; v3 += b1;
                s += v0 + v1 + v2 + v3;
                ss += v0 * v0 + v1 * v1 + v2 * v2 + v3 * v3;
            }
            *(float2*)(C + (size_t)row0 * N + col)       = make_float2(v0, v1);
            *(float2*)(C + (size_t)(row0 + 8) * N + col) = make_float2(v2, v3);
        }
    }

    if (EPI == 2) {
        red_s[tid] = s; red_ss[tid] = ss;
        __syncthreads();
        for (int off = 128; off > 0; off >>= 1) {
            if (tid < off) { red_s[tid] += red_s[tid + off];
                             red_ss[tid] += red_ss[tid + off]; }
            __syncthreads();
        }
        if (tid == 0) {
            int pid = bm * gridDim.x + bn;
            g_psum[2 * pid] = red_s[0];
            g_psum[2 * pid + 1] = red_ss[0];
        }
    }
}

// ---------- fused causal conv + SiLU + x_proj + dt_proj + pack -----------
#define TOK 16
__global__ void __launch_bounds__(512)
convproj_kernel(const float* __restrict__ conv_w, const float* __restrict__ conv_b,
                const float* __restrict__ x_proj_w, const float* __restrict__ dt_proj_w,
                const float* __restrict__ dt_proj_b, const float* __restrict__ D_skip)
{
    const int b  = blockIdx.x >> 7;
    const int l0 = (blockIdx.x & 127) * TOK;
    const int d  = threadIdx.x;

    __shared__ float xc_s[TOK][512];
    __shared__ float xdbl_s[TOK][48];

    {
        float4 cw = ((const float4*)conv_w)[d];
        float cb = conv_b[d];
        const float* xcol = g_xz + (size_t)(b * 2048 + l0) * 1024 + d;
        float w0 = (l0 - 3 >= 0) ? xcol[-3 * 1024] : 0.f;
        float w1 = (l0 - 2 >= 0) ? xcol[-2 * 1024] : 0.f;
        float w2 = (l0 - 1 >= 0) ? xcol[-1 * 1024] : 0.f;
#pragma unroll
        for (int t = 0; t < TOK; ++t) {
            float cur = xcol[t * 1024];
            float acc = cb;
            acc = fmaf(w0, cw.x, acc);
            acc = fmaf(w1, cw.y, acc);
            acc = fmaf(w2, cw.z, acc);
            acc = fmaf(cur, cw.w, acc);
            xc_s[t][d] = silu_f(acc);
            w0 = w1; w1 = w2; w2 = cur;
        }
    }
    __syncthreads();

    {
        const int warp = d >> 5, lane = d & 31;
        float4 wv[3][4];
        const float4* xw4 = (const float4*)x_proj_w;
#pragma unroll
        for (int jj = 0; jj < 3; ++jj) {
            const float4* wrow = xw4 + (size_t)(warp * 3 + jj) * 128;
#pragma unroll
            for (int q = 0; q < 4; ++q)
                wv[jj][q] = wrow[lane + q * 32];
        }
#pragma unroll
        for (int t = 0; t < TOK; ++t) {
            float4 xv[4];
            const float4* xr = (const float4*)&xc_s[t][0];
#pragma unroll
            for (int q = 0; q < 4; ++q) xv[q] = xr[lane + q * 32];
            float a0 = 0.f, a1 = 0.f, a2 = 0.f;
#pragma unroll
            for (int q = 0; q < 4; ++q) {
                a0 = fmaf(xv[q].x, wv[0][q].x, a0); a0 = fmaf(xv[q].y, wv[0][q].y, a0);
                a0 = fmaf(xv[q].z, wv[0][q].z, a0); a0 = fmaf(xv[q].w, wv[0][q].w, a0);
                a1 = fmaf(xv[q].x, wv[1][q].x, a1); a1 = fmaf(xv[q].y, wv[1][q].y, a1);
                a1 = fmaf(xv[q].z, wv[1][q].z, a1); a1 = fmaf(xv[q].w, wv[1][q].w, a1);
                a2 = fmaf(xv[q].x, wv[2][q].x, a2); a2 = fmaf(xv[q].y, wv[2][q].y, a2);
                a2 = fmaf(xv[q].z, wv[2][q].z, a2); a2 = fmaf(xv[q].w, wv[2][q].w, a2);
            }
#pragma unroll
            for (int off = 16; off; off >>= 1) {
                a0 += __shfl_xor_sync(0xffffffffu, a0, off);
                a1 += __shfl_xor_sync(0xffffffffu, a1, off);
                a2 += __shfl_xor_sync(0xffffffffu, a2, off);
            }
            if (lane == 0) {
                xdbl_s[t][warp * 3 + 0] = a0;
                xdbl_s[t][warp * 3 + 1] = a1;
                xdbl_s[t][warp * 3 + 2] = a2;
            }
        }
    }
    __syncthreads();

    {
        const float4* dw = (const float4*)(dt_proj_w + d * 16);
        float4 dw0 = dw[0], dw1 = dw[1], dw2 = dw[2], dw3 = dw[3];
        const float dtb = dt_proj_b[d];
        const float Dv = D_skip[d];
        const float* zptr = g_xz + (size_t)(b * 2048 + l0) * 1024 + 512 + d;
        float4* outp = g_scanin + (size_t)(b * 2048 + l0) * 512 + d;
#pragma unroll
        for (int t = 0; t < TOK; ++t) {
            const float4* xr = (const float4*)&xdbl_s[t][0];
            float4 x0 = xr[0], x1 = xr[1], x2 = xr[2], x3 = xr[3];
            float dt = dtb;
            dt = fmaf(x0.x, dw0.x, dt); dt = fmaf(x0.y, dw0.y, dt);
            dt = fmaf(x0.z, dw0.z, dt); dt = fmaf(x0.w, dw0.w, dt);
            dt = fmaf(x1.x, dw1.x, dt); dt = fmaf(x1.y, dw1.y, dt);
            dt = fmaf(x1.z, dw1.z, dt); dt = fmaf(x1.w, dw1.w, dt);
            dt = fmaf(x2.x, dw2.x, dt); dt = fmaf(x2.y, dw2.y, dt);
            dt = fmaf(x2.z, dw2.z, dt); dt = fmaf(x2.w, dw2.w, dt);
            dt = fmaf(x3.x, dw3.x, dt); dt = fmaf(x3.y, dw3.y, dt);
            dt = fmaf(x3.z, dw3.z, dt); dt = fmaf(x3.w, dw3.w, dt);
            float delta = (dt > 20.f) ? dt : __logf(1.f + __expf(dt));
            float xc = xc_s[t][d];
            float sz = zptr[(size_t)t * 1024];
            outp[(size_t)t * 512] = make_float4(delta, delta * xc, sz, xc * Dv);
        }
    }

    if (d < TOK * DSTATE) {
        const int t = d >> 4, n = d & 15;
        g_bc[(size_t)(b * 2048 + l0 + t) * 16 + n] =
            make_float2(xdbl_s[t][16 + n], xdbl_s[t][32 + n]);
    }
}

// ---------------- diagonal selective scan (v5: cp.async pipeline) ---------
// warp = 4 channels x 8 lanes x 2 states/lane (proven v3 mapping).
// gmem->smem staging via cp.async, DEPTH=4 stages of 8 timesteps, warp-private.
#define SDEPTH 4
__global__ void __launch_bounds__(128)
scan_kernel(const float* __restrict__ A_log)
{
    __shared__ float4 sv[4][SDEPTH][8][4];    // [warp][stage][t][dsub]
    __shared__ float4 sbc[4][SDEPTH][8][8];   // [warp][stage][t][li]

    const int wid = threadIdx.x >> 5;
    const int lane = threadIdx.x & 31;
    const int w = blockIdx.x * 4 + wid;      // 0..2047
    const int b = w >> 7;
    const int dbase = (w & 127) * 4;
    const int li = lane & 7;
    const int dsub = lane >> 3;
    const int d = dbase + dsub;
    const int n0 = li * 2;

    const float LOG2E = 1.44269504f;
    const float An0 = -__expf(A_log[d * 16 + n0])     * LOG2E;
    const float An1 = -__expf(A_log[d * 16 + n0 + 1]) * LOG2E;

    const float4* vsrc  = g_scanin + (size_t)(b * 2048) * 512;
    const float4* bcsrc = reinterpret_cast<const float4*>(g_bc)
                          + (size_t)(b * 2048) * 8;
    float* yp = g_y + (size_t)(b * 2048) * 512 + d;

    // load-role lane mappings
    const int lv_t = lane >> 2, lv_d = lane & 3;    // v tile: 8t x 4d
    const int lb_t = lane >> 3, lb_q = lane & 7;    // bc tile: 2x (4t x 8q)

    float h0 = 0.f, h1 = 0.f;

    // prologue: stages 0..2
#pragma unroll
    for (int s = 0; s < SDEPTH - 1; ++s) {
        const int tb = s * 8;
        uint32_t dv = (uint32_t)__cvta_generic_to_shared(&sv[wid][s][lv_t][lv_d]);
        const float4* pv = vsrc + (size_t)(tb + lv_t) * 512 + (dbase + lv_d);
        asm volatile("cp.async.cg.shared.global [%0], [%1], 16;"
                     :: "r"(dv), "l"(pv) : "memory");
        uint32_t db0 = (uint32_t)__cvta_generic_to_shared(&sbc[wid][s][lb_t][lb_q]);
        const float4* pb0 = bcsrc + (size_t)(tb + lb_t) * 8 + lb_q;
        asm volatile("cp.async.cg.shared.global [%0], [%1], 16;"
                     :: "r"(db0), "l"(pb0) : "memory");
        uint32_t db1 = (uint32_t)__cvta_generic_to_shared(&sbc[wid][s][lb_t + 4][lb_q]);
        const float4* pb1 = bcsrc + (size_t)(tb + lb_t + 4) * 8 + lb_q;
        asm volatile("cp.async.cg.shared.global [%0], [%1], 16;"
                     :: "r"(db1), "l"(pb1) : "memory");
        asm volatile("cp.async.commit_group;" ::: "memory");
    }

    for (int k = 0; k < 256; ++k) {
        asm volatile("cp.async.wait_group %0;" :: "n"(SDEPTH - 2) : "memory");
        __syncwarp();
        const int cs = k & (SDEPTH - 1);
#pragma unroll
        for (int j = 0; j < 8; ++j) {
            float4 v  = sv[wid][cs][j][dsub];   // (delta, delta*xc, silu(z), xc*D)
            float4 bc = sbc[wid][cs][j][li];    // (B_n0, C_n0, B_n0+1, C_n0+1)
            float dA0 = exp2f(v.x * An0);
            float dA1 = exp2f(v.x * An1);
            h0 = fmaf(dA0, h0, v.y * bc.x);
            h1 = fmaf(dA1, h1, v.y * bc.z);
            float p = fmaf(h0, bc.y, h1 * bc.w);
            p += __shfl_xor_sync(0xffffffffu, p, 1);
            p += __shfl_xor_sync(0xffffffffu, p, 2);
            p += __shfl_xor_sync(0xffffffffu, p, 4);
            if (li == 0)
                yp[(size_t)(k * 8 + j) * 512] = (p + v.w) * v.z;
        }
        const int ks = k + SDEPTH - 1;
        if (ks < 256) {
            const int s = ks & (SDEPTH - 1);
            const int tb = ks * 8;
            uint32_t dv = (uint32_t)__cvta_generic_to_shared(&sv[wid][s][lv_t][lv_d]);
            const float4* pv = vsrc + (size_t)(tb + lv_t) * 512 + (dbase + lv_d);
            asm volatile("cp.async.cg.shared.global [%0], [%1], 16;"
                         :: "r"(dv), "l"(pv) : "memory");
            uint32_t db0 = (uint32_t)__cvta_generic_to_shared(&sbc[wid][s][lb_t][lb_q]);
            const float4* pb0 = bcsrc + (size_t)(tb + lb_t) * 8 + lb_q;
            asm volatile("cp.async.cg.shared.global [%0], [%1], 16;"
                         :: "r"(db0), "l"(pb0) : "memory");
            uint32_t db1 = (uint32_t)__cvta_generic_to_shared(&sbc[wid][s][lb_t + 4][lb_q]);
            const float4* pb1 = bcsrc + (size_t)(tb + lb_t + 4) * 8 + lb_q;
            asm volatile("cp.async.cg.shared.global [%0], [%1], 16;"
                         :: "r"(db1), "l"(pb1) : "memory");
        }
        // unconditional commit keeps wait_group arithmetic exact (empty ok)
        asm volatile("cp.async.commit_group;" ::: "memory");
    }
}

// ------------------------- LayerNorm stats + apply ------------------------
__global__ void stats_kernel()
{
    int b = threadIdx.x;
    if (b >= BATCH) return;
    double s = 0.0, ss = 0.0;
    for (int bm = b * 16; bm < b * 16 + 16; ++bm)
        for (int bn = 0; bn < 2; ++bn) {
            int pid = bm * 2 + bn;
            s  += (double)g_psum[2 * pid];
            ss += (double)g_psum[2 * pid + 1];
        }
    const double nd = (double)LSEQ * NOUT;
    double mu = s / nd;
    double var = ss / nd - mu * mu;
    g_stats[b] = make_float2((float)mu, (float)rsqrt(var + 1e-5));
}

__global__ void __launch_bounds__(256)
norm_kernel(float* __restrict__ out, const float* __restrict__ lnw,
            const float* __restrict__ lnb)
{
    size_t i4 = (size_t)blockIdx.x * 256 + threadIdx.x;
    size_t base = i4 * 4;
    int row = (int)(base >> 8);
    int b = row >> 11;
    int l = row & 2047;
    int o = (int)(base & 255);
    float2 st = g_stats[b];
    float4 v = *(float4*)(out + base);
    const float4 w  = *(const float4*)(lnw + (size_t)l * 256 + o);
    const float4 bb = *(const float4*)(lnb + (size_t)l * 256 + o);
    v.x = (v.x - st.x) * st.y * w.x + bb.x;
    v.y = (v.y - st.x) * st.y * w.y + bb.y;
    v.z = (v.z - st.x) * st.y * w.z + bb.z;
    v.w = (v.w - st.x) * st.y * w.w + bb.w;
    *(float4*)(out + base) = v;
}

// ------------------------------- launch -----------------------------------
extern "C" void kernel_launch(void* const* d_in, const int* in_sizes, int n_in,
                              void* d_out, int out_size)
{
    const float* inputs    = (const float*)d_in[0];
    const float* in_proj_w = (const float*)d_in[1];
    const float* conv_w    = (const float*)d_in[2];
    const float* conv_b    = (const float*)d_in[3];
    const float* x_proj_w  = (const float*)d_in[4];
    const float* dt_proj_w = (const float*)d_in[5];
    const float* dt_proj_b = (const float*)d_in[6];
    const float* A_log     = (const float*)d_in[7];
    const float* D_skip    = (const float*)d_in[8];
    const float* out_proj_w= (const float*)d_in[9];
    const float* dim_w     = (const float*)d_in[10];
    const float* dim_b     = (const float*)d_in[11];
    const float* ln_w      = (const float*)d_in[12];
    const float* ln_b      = (const float*)d_in[13];
    float* out = (float*)d_out;

    float *xz, *y, *t1;
    cudaGetSymbolAddress((void**)&xz, g_xz);
    cudaGetSymbolAddress((void**)&y,  g_y);
    cudaGetSymbolAddress((void**)&t1, g_t1);

    // 1) xz = inputs @ in_proj_w^T  [32768 x 1024], silu on z half (bn>=4)
    gemm_bf16_kernel<3><<<dim3(1024 / 128, NROWS / 128), 256>>>(
        inputs, in_proj_w, xz, 1024, 256, nullptr);

    // 2) conv + silu + x_proj + dt_proj, packed scan inputs
    convproj_kernel<<<NROWS / TOK, 512>>>(conv_w, conv_b, x_proj_w,
                                          dt_proj_w, dt_proj_b, D_skip);

    // 3) selective scan (v5: cp.async depth-4 pipeline)
    scan_kernel<<<512, 128>>>(A_log);

    // 4) t1 = silu(y @ out_proj_w^T)  [32768 x 256]
    gemm_bf16_kernel<1><<<dim3(256 / 128, NROWS / 128), 256>>>(
        y, out_proj_w, t1, 256, 512, nullptr);

    // 5) out = t1 @ dim_w^T + dim_b, + per-block partial sums
    gemm_bf16_kernel<2><<<dim3(256 / 128, NROWS / 128), 256>>>(
        t1, dim_w, out, 256, 256, dim_b);

    // 6) per-batch LayerNorm
    stats_kernel<<<1, 32>>>();
    norm_kernel<<<(NROWS * NOUT / 4) / 256, 256>>>(out, ln_w, ln_b);
}

// round 9
// speedup vs baseline: 2.0922x; 1.0254x over previous
#include <cuda_runtime.h>
#include <math.h>
#include <stdint.h>

#define BATCH   16
#define LSEQ    2048
#define DMODEL  256
#define DINNER  512
#define DSTATE  16
#define NOUT    256
#define NROWS   (BATCH*LSEQ)   /* 32768 */

// ---------------- device scratch (no allocations allowed) ----------------
__device__ float  g_xz[(size_t)NROWS * 1024];        // in_proj output (x | silu(z))
__device__ float4 g_scanin[(size_t)NROWS * DINNER];  // (delta, delta*xc, silu(z), xc*D)
__device__ float2 g_bc[(size_t)NROWS * DSTATE];      // (B_n, C_n) interleaved
__device__ float  g_y[(size_t)NROWS * DINNER];       // scan output (pre out_proj)
__device__ float  g_t1[(size_t)NROWS * NOUT];        // silu(out_proj)
__device__ float  g_psum[512 * 2];                   // per-block (sum, sumsq)
__device__ float2 g_stats[BATCH];                    // (mean, rstd)

__device__ __forceinline__ float silu_f(float v) {
    return v / (1.f + __expf(-v));
}

// ---------------------------- bf16 helpers --------------------------------
__device__ __forceinline__ uint32_t pack_bf16x2(float hi, float lo) {
    uint32_t r;
    asm("cvt.rn.bf16x2.f32 %0, %1, %2;" : "=r"(r) : "f"(hi), "f"(lo));
    return r;
}
__device__ __forceinline__ float lo_f32(uint32_t p) {
    return __uint_as_float(p << 16);
}
__device__ __forceinline__ float hi_f32(uint32_t p) {
    return __uint_as_float(p & 0xffff0000u);
}
__device__ __forceinline__ void mma_bf16(float* c, const uint32_t* a,
                                         const uint32_t* b) {
    asm volatile(
        "mma.sync.aligned.m16n8k16.row.col.f32.bf16.bf16.f32 "
        "{%0,%1,%2,%3}, {%4,%5,%6,%7}, {%8,%9}, {%0,%1,%2,%3};"
        : "+f"(c[0]), "+f"(c[1]), "+f"(c[2]), "+f"(c[3])
        : "r"(a[0]), "r"(a[1]), "r"(a[2]), "r"(a[3]), "r"(b[0]), "r"(b[1]));
}

// -------------------- 3x-bf16 tensor-core NT GEMM (v2) --------------------
// cp.async 4-stage raw fp32 staging (thread-private slots), double-buffered
// bf16-split smem, 1 __syncthreads per ktile.
#define KSTR 264
#define NSTAGE 4
#define RAW_F4   (NSTAGE * 512)                 // per matrix
#define BUFN     (4 * KSTR)
#define GSM_BYTES (2 * RAW_F4 * 16 + 4 * 2 * BUFN * 4)  // 65536 + 33792 = 99328

template <int EPI>
__global__ void __launch_bounds__(256, 2)
gemm_bf16_kernel(const float* __restrict__ A, const float* __restrict__ B,
                 float* __restrict__ C, int N, int K,
                 const float* __restrict__ bias)
{
    extern __shared__ char sm[];
    float4*  rawA = (float4*)sm;
    float4*  rawB = rawA + RAW_F4;
    uint32_t* AhP = (uint32_t*)(rawB + RAW_F4);
    uint32_t* AlP = AhP + 2 * BUFN;
    uint32_t* BhP = AlP + 2 * BUFN;
    uint32_t* BlP = BhP + 2 * BUFN;
    __shared__ float red_s[256], red_ss[256];

    const int tid = threadIdx.x;
    const int wid = tid >> 5;
    const int lane = tid & 31;
    const int grp = lane >> 2;       // 0..7
    const int tg  = lane & 3;        // 0..3
    const int warp_m = wid & 1;      // 2 x 64 rows
    const int warp_n = wid >> 1;     // 4 x 32 cols
    const int bm = blockIdx.y, bn = blockIdx.x;

    const int lrow = tid >> 2;       // 0..63
    const int lkq  = tid & 3;        // k-quad (4 floats each)

    const int k2a = lkq * 2, k2b = lkq * 2 + 1;
    const int sa_row = k2a & 3, sa_kh = k2a >> 2;
    const int sb_row = k2b & 3, sb_kh = k2b >> 2;

    const int nkt = K >> 4;
    const float* Ag = A + (size_t)(bm * 128 + lrow) * K + lkq * 4;
    const float* Bg = B + (size_t)(bn * 128 + lrow) * K + lkq * 4;
    const size_t rstep = (size_t)64 * K;

    float acc[4][4][4] = {};

#define GISSUE(ktv) do {                                                     \
    const int _kt = (ktv);                                                   \
    if (_kt < nkt) {                                                         \
        const int _s = _kt & (NSTAGE - 1);                                   \
        uint32_t _da0 = (uint32_t)__cvta_generic_to_shared(&rawA[_s*512 + tid]);     \
        uint32_t _da1 = (uint32_t)__cvta_generic_to_shared(&rawA[_s*512 + 256+tid]); \
        uint32_t _db0 = (uint32_t)__cvta_generic_to_shared(&rawB[_s*512 + tid]);     \
        uint32_t _db1 = (uint32_t)__cvta_generic_to_shared(&rawB[_s*512 + 256+tid]); \
        const float* _pa = Ag + _kt * 16;                                    \
        const float* _pb = Bg + _kt * 16;                                    \
        asm volatile("cp.async.cg.shared.global [%0], [%1], 16;"             \
                     :: "r"(_da0), "l"(_pa) : "memory");                     \
        asm volatile("cp.async.cg.shared.global [%0], [%1], 16;"             \
                     :: "r"(_da1), "l"(_pa + rstep) : "memory");             \
        asm volatile("cp.async.cg.shared.global [%0], [%1], 16;"             \
                     :: "r"(_db0), "l"(_pb) : "memory");                     \
        asm volatile("cp.async.cg.shared.global [%0], [%1], 16;"             \
                     :: "r"(_db1), "l"(_pb + rstep) : "memory");             \
    }                                                                        \
    asm volatile("cp.async.commit_group;" ::: "memory");                    \
} while (0)

    GISSUE(0); GISSUE(1); GISSUE(2);

    for (int kt = 0; kt < nkt; ++kt) {
        asm volatile("cp.async.wait_group %0;" :: "n"(2) : "memory");
        const int rs = kt & (NSTAGE - 1);
        const int bufo = (kt & 1) * BUFN;

        // read back thread-private raw tiles and convert/split into bf16 smem
#pragma unroll
        for (int rr = 0; rr < 2; ++rr) {
            const int r = lrow + rr * 64;
            float4 va = rawA[rs * 512 + rr * 256 + tid];
            float4 vb = rawB[rs * 512 + rr * 256 + tid];
            uint32_t h01 = pack_bf16x2(va.y, va.x);
            uint32_t h23 = pack_bf16x2(va.w, va.z);
            uint32_t l01 = pack_bf16x2(va.y - hi_f32(h01), va.x - lo_f32(h01));
            uint32_t l23 = pack_bf16x2(va.w - hi_f32(h23), va.z - lo_f32(h23));
            AhP[bufo + sa_row * KSTR + r * 2 + sa_kh] = h01;
            AlP[bufo + sa_row * KSTR + r * 2 + sa_kh] = l01;
            AhP[bufo + sb_row * KSTR + r * 2 + sb_kh] = h23;
            AlP[bufo + sb_row * KSTR + r * 2 + sb_kh] = l23;
            h01 = pack_bf16x2(vb.y, vb.x);
            h23 = pack_bf16x2(vb.w, vb.z);
            l01 = pack_bf16x2(vb.y - hi_f32(h01), vb.x - lo_f32(h01));
            l23 = pack_bf16x2(vb.w - hi_f32(h23), vb.z - lo_f32(h23));
            BhP[bufo + sa_row * KSTR + r * 2 + sa_kh] = h01;
            BlP[bufo + sa_row * KSTR + r * 2 + sa_kh] = l01;
            BhP[bufo + sb_row * KSTR + r * 2 + sb_kh] = h23;
            BlP[bufo + sb_row * KSTR + r * 2 + sb_kh] = l23;
        }

        GISSUE(kt + 3);          // distinct slot from rs (4 stages), safe
        __syncthreads();

        // fragment loads (LDS.64, conflict-free) + 3-pass MMA
        uint2 af[4][2], bh[4], bl[4];
#pragma unroll
        for (int mi = 0; mi < 4; ++mi) {
            const int m = warp_m * 64 + mi * 16 + grp;
            af[mi][0] = *(const uint2*)&AhP[bufo + tg * KSTR + 2 * m];
            af[mi][1] = *(const uint2*)&AhP[bufo + tg * KSTR + 2 * (m + 8)];
        }
#pragma unroll
        for (int ni = 0; ni < 4; ++ni) {
            const int n = warp_n * 32 + ni * 8 + grp;
            bh[ni] = *(const uint2*)&BhP[bufo + tg * KSTR + 2 * n];
            bl[ni] = *(const uint2*)&BlP[bufo + tg * KSTR + 2 * n];
        }
#pragma unroll
        for (int mi = 0; mi < 4; ++mi) {
            const uint32_t a[4] = {af[mi][0].x, af[mi][1].x,
                                   af[mi][0].y, af[mi][1].y};
#pragma unroll
            for (int ni = 0; ni < 4; ++ni) {
                const uint32_t b0[2] = {bh[ni].x, bh[ni].y};
                const uint32_t b1[2] = {bl[ni].x, bl[ni].y};
                mma_bf16(acc[mi][ni], a, b0);
                mma_bf16(acc[mi][ni], a, b1);
            }
        }
#pragma unroll
        for (int mi = 0; mi < 4; ++mi) {
            const int m = warp_m * 64 + mi * 16 + grp;
            af[mi][0] = *(const uint2*)&AlP[bufo + tg * KSTR + 2 * m];
            af[mi][1] = *(const uint2*)&AlP[bufo + tg * KSTR + 2 * (m + 8)];
        }
#pragma unroll
        for (int mi = 0; mi < 4; ++mi) {
            const uint32_t a[4] = {af[mi][0].x, af[mi][1].x,
                                   af[mi][0].y, af[mi][1].y};
#pragma unroll
            for (int ni = 0; ni < 4; ++ni) {
                const uint32_t b0[2] = {bh[ni].x, bh[ni].y};
                mma_bf16(acc[mi][ni], a, b0);
            }
        }
    }

    float s = 0.f, ss = 0.f;
    const bool dos = (EPI == 1) || (EPI == 3 && bn >= 4);
#pragma unroll
    for (int mi = 0; mi < 4; ++mi) {
        const int row0 = bm * 128 + warp_m * 64 + mi * 16 + grp;
#pragma unroll
        for (int ni = 0; ni < 4; ++ni) {
            const int col = bn * 128 + warp_n * 32 + ni * 8 + tg * 2;
            float v0 = acc[mi][ni][0], v1 = acc[mi][ni][1];
            float v2 = acc[mi][ni][2], v3 = acc[mi][ni][3];
            if (dos) { v0 = silu_f(v0); v1 = silu_f(v1);
                       v2 = silu_f(v2); v3 = silu_f(v3); }
            if (EPI == 2) {
                const float b0 = bias[col], b1 = bias[col + 1];
                v0 += b0; v1 += b1; v2 += b0; v3 += b1;
                s += v0 + v1 + v2 + v3;
                ss += v0 * v0 + v1 * v1 + v2 * v2 + v3 * v3;
            }
            *(float2*)(C + (size_t)row0 * N + col)       = make_float2(v0, v1);
            *(float2*)(C + (size_t)(row0 + 8) * N + col) = make_float2(v2, v3);
        }
    }

    if (EPI == 2) {
        red_s[tid] = s; red_ss[tid] = ss;
        __syncthreads();
        for (int off = 128; off > 0; off >>= 1) {
            if (tid < off) { red_s[tid] += red_s[tid + off];
                             red_ss[tid] += red_ss[tid + off]; }
            __syncthreads();
        }
        if (tid == 0) {
            int pid = bm * gridDim.x + bn;
            g_psum[2 * pid] = red_s[0];
            g_psum[2 * pid + 1] = red_ss[0];
        }
    }
}

// ---------- fused causal conv + SiLU + x_proj + dt_proj + pack -----------
#define TOK 16
__global__ void __launch_bounds__(512)
convproj_kernel(const float* __restrict__ conv_w, const float* __restrict__ conv_b,
                const float* __restrict__ x_proj_w, const float* __restrict__ dt_proj_w,
                const float* __restrict__ dt_proj_b, const float* __restrict__ D_skip)
{
    const int b  = blockIdx.x >> 7;
    const int l0 = (blockIdx.x & 127) * TOK;
    const int d  = threadIdx.x;

    __shared__ float xc_s[TOK][512];
    __shared__ float xdbl_s[TOK][48];

    {
        float4 cw = ((const float4*)conv_w)[d];
        float cb = conv_b[d];
        const float* xcol = g_xz + (size_t)(b * 2048 + l0) * 1024 + d;
        float w0 = (l0 - 3 >= 0) ? xcol[-3 * 1024] : 0.f;
        float w1 = (l0 - 2 >= 0) ? xcol[-2 * 1024] : 0.f;
        float w2 = (l0 - 1 >= 0) ? xcol[-1 * 1024] : 0.f;
#pragma unroll
        for (int t = 0; t < TOK; ++t) {
            float cur = xcol[t * 1024];
            float acc = cb;
            acc = fmaf(w0, cw.x, acc);
            acc = fmaf(w1, cw.y, acc);
            acc = fmaf(w2, cw.z, acc);
            acc = fmaf(cur, cw.w, acc);
            xc_s[t][d] = silu_f(acc);
            w0 = w1; w1 = w2; w2 = cur;
        }
    }
    __syncthreads();

    {
        const int warp = d >> 5, lane = d & 31;
        float4 wv[3][4];
        const float4* xw4 = (const float4*)x_proj_w;
#pragma unroll
        for (int jj = 0; jj < 3; ++jj) {
            const float4* wrow = xw4 + (size_t)(warp * 3 + jj) * 128;
#pragma unroll
            for (int q = 0; q < 4; ++q)
                wv[jj][q] = wrow[lane + q * 32];
        }
#pragma unroll
        for (int t = 0; t < TOK; ++t) {
            float4 xv[4];
            const float4* xr = (const float4*)&xc_s[t][0];
#pragma unroll
            for (int q = 0; q < 4; ++q) xv[q] = xr[lane + q * 32];
            float a0 = 0.f, a1 = 0.f, a2 = 0.f;
#pragma unroll
            for (int q = 0; q < 4; ++q) {
                a0 = fmaf(xv[q].x, wv[0][q].x, a0); a0 = fmaf(xv[q].y, wv[0][q].y, a0);
                a0 = fmaf(xv[q].z, wv[0][q].z, a0); a0 = fmaf(xv[q].w, wv[0][q].w, a0);
                a1 = fmaf(xv[q].x, wv[1][q].x, a1); a1 = fmaf(xv[q].y, wv[1][q].y, a1);
                a1 = fmaf(xv[q].z, wv[1][q].z, a1); a1 = fmaf(xv[q].w, wv[1][q].w, a1);
                a2 = fmaf(xv[q].x, wv[2][q].x, a2); a2 = fmaf(xv[q].y, wv[2][q].y, a2);
                a2 = fmaf(xv[q].z, wv[2][q].z, a2); a2 = fmaf(xv[q].w, wv[2][q].w, a2);
            }
#pragma unroll
            for (int off = 16; off; off >>= 1) {
                a0 += __shfl_xor_sync(0xffffffffu, a0, off);
                a1 += __shfl_xor_sync(0xffffffffu, a1, off);
                a2 += __shfl_xor_sync(0xffffffffu, a2, off);
            }
            if (lane == 0) {
                xdbl_s[t][warp * 3 + 0] = a0;
                xdbl_s[t][warp * 3 + 1] = a1;
                xdbl_s[t][warp * 3 + 2] = a2;
            }
        }
    }
    __syncthreads();

    {
        const float4* dw = (const float4*)(dt_proj_w + d * 16);
        float4 dw0 = dw[0], dw1 = dw[1], dw2 = dw[2], dw3 = dw[3];
        const float dtb = dt_proj_b[d];
        const float Dv = D_skip[d];
        const float* zptr = g_xz + (size_t)(b * 2048 + l0) * 1024 + 512 + d;
        float4* outp = g_scanin + (size_t)(b * 2048 + l0) * 512 + d;
#pragma unroll
        for (int t = 0; t < TOK; ++t) {
            const float4* xr = (const float4*)&xdbl_s[t][0];
            float4 x0 = xr[0], x1 = xr[1], x2 = xr[2], x3 = xr[3];
            float dt = dtb;
            dt = fmaf(x0.x, dw0.x, dt); dt = fmaf(x0.y, dw0.y, dt);
            dt = fmaf(x0.z, dw0.z, dt); dt = fmaf(x0.w, dw0.w, dt);
            dt = fmaf(x1.x, dw1.x, dt); dt = fmaf(x1.y, dw1.y, dt);
            dt = fmaf(x1.z, dw1.z, dt); dt = fmaf(x1.w, dw1.w, dt);
            dt = fmaf(x2.x, dw2.x, dt); dt = fmaf(x2.y, dw2.y, dt);
            dt = fmaf(x2.z, dw2.z, dt); dt = fmaf(x2.w, dw2.w, dt);
            dt = fmaf(x3.x, dw3.x, dt); dt = fmaf(x3.y, dw3.y, dt);
            dt = fmaf(x3.z, dw3.z, dt); dt = fmaf(x3.w, dw3.w, dt);
            float delta = (dt > 20.f) ? dt : __logf(1.f + __expf(dt));
            float xc = xc_s[t][d];
            float sz = zptr[(size_t)t * 1024];
            outp[(size_t)t * 512] = make_float4(delta, delta * xc, sz, xc * Dv);
        }
    }

    if (d < TOK * DSTATE) {
        const int t = d >> 4, n = d & 15;
        g_bc[(size_t)(b * 2048 + l0 + t) * 16 + n] =
            make_float2(xdbl_s[t][16 + n], xdbl_s[t][32 + n]);
    }
}

// ---------------- diagonal selective scan (v5: cp.async pipeline) ---------
#define SDEPTH 4
__global__ void __launch_bounds__(128)
scan_kernel(const float* __restrict__ A_log)
{
    __shared__ float4 sv[4][SDEPTH][8][4];
    __shared__ float4 sbc[4][SDEPTH][8][8];

    const int wid = threadIdx.x >> 5;
    const int lane = threadIdx.x & 31;
    const int w = blockIdx.x * 4 + wid;
    const int b = w >> 7;
    const int dbase = (w & 127) * 4;
    const int li = lane & 7;
    const int dsub = lane >> 3;
    const int d = dbase + dsub;
    const int n0 = li * 2;

    const float LOG2E = 1.44269504f;
    const float An0 = -__expf(A_log[d * 16 + n0])     * LOG2E;
    const float An1 = -__expf(A_log[d * 16 + n0 + 1]) * LOG2E;

    const float4* vsrc  = g_scanin + (size_t)(b * 2048) * 512;
    const float4* bcsrc = reinterpret_cast<const float4*>(g_bc)
                          + (size_t)(b * 2048) * 8;
    float* yp = g_y + (size_t)(b * 2048) * 512 + d;

    const int lv_t = lane >> 2, lv_d = lane & 3;
    const int lb_t = lane >> 3, lb_q = lane & 7;

    float h0 = 0.f, h1 = 0.f;

#pragma unroll
    for (int s = 0; s < SDEPTH - 1; ++s) {
        const int tb = s * 8;
        uint32_t dv = (uint32_t)__cvta_generic_to_shared(&sv[wid][s][lv_t][lv_d]);
        const float4* pv = vsrc + (size_t)(tb + lv_t) * 512 + (dbase + lv_d);
        asm volatile("cp.async.cg.shared.global [%0], [%1], 16;"
                     :: "r"(dv), "l"(pv) : "memory");
        uint32_t db0 = (uint32_t)__cvta_generic_to_shared(&sbc[wid][s][lb_t][lb_q]);
        const float4* pb0 = bcsrc + (size_t)(tb + lb_t) * 8 + lb_q;
        asm volatile("cp.async.cg.shared.global [%0], [%1], 16;"
                     :: "r"(db0), "l"(pb0) : "memory");
        uint32_t db1 = (uint32_t)__cvta_generic_to_shared(&sbc[wid][s][lb_t + 4][lb_q]);
        const float4* pb1 = bcsrc + (size_t)(tb + lb_t + 4) * 8 + lb_q;
        asm volatile("cp.async.cg.shared.global [%0], [%1], 16;"
                     :: "r"(db1), "l"(pb1) : "memory");
        asm volatile("cp.async.commit_group;" ::: "memory");
    }

    for (int k = 0; k < 256; ++k) {
        asm volatile("cp.async.wait_group %0;" :: "n"(SDEPTH - 2) : "memory");
        __syncwarp();
        const int cs = k & (SDEPTH - 1);
#pragma unroll
        for (int j = 0; j < 8; ++j) {
            float4 v  = sv[wid][cs][j][dsub];
            float4 bc = sbc[wid][cs][j][li];
            float dA0 = exp2f(v.x * An0);
            float dA1 = exp2f(v.x * An1);
            h0 = fmaf(dA0, h0, v.y * bc.x);
            h1 = fmaf(dA1, h1, v.y * bc.z);
            float p = fmaf(h0, bc.y, h1 * bc.w);
            p += __shfl_xor_sync(0xffffffffu, p, 1);
            p += __shfl_xor_sync(0xffffffffu, p, 2);
            p += __shfl_xor_sync(0xffffffffu, p, 4);
            if (li == 0)
                yp[(size_t)(k * 8 + j) * 512] = (p + v.w) * v.z;
        }
        const int ks = k + SDEPTH - 1;
        if (ks < 256) {
            const int s = ks & (SDEPTH - 1);
            const int tb = ks * 8;
            uint32_t dv = (uint32_t)__cvta_generic_to_shared(&sv[wid][s][lv_t][lv_d]);
            const float4* pv = vsrc + (size_t)(tb + lv_t) * 512 + (dbase + lv_d);
            asm volatile("cp.async.cg.shared.global [%0], [%1], 16;"
                         :: "r"(dv), "l"(pv) : "memory");
            uint32_t db0 = (uint32_t)__cvta_generic_to_shared(&sbc[wid][s][lb_t][lb_q]);
            const float4* pb0 = bcsrc + (size_t)(tb + lb_t) * 8 + lb_q;
            asm volatile("cp.async.cg.shared.global [%0], [%1], 16;"
                         :: "r"(db0), "l"(pb0) : "memory");
            uint32_t db1 = (uint32_t)__cvta_generic_to_shared(&sbc[wid][s][lb_t + 4][lb_q]);
            const float4* pb1 = bcsrc + (size_t)(tb + lb_t + 4) * 8 + lb_q;
            asm volatile("cp.async.cg.shared.global [%0], [%1], 16;"
                         :: "r"(db1), "l"(pb1) : "memory");
        }
        asm volatile("cp.async.commit_group;" ::: "memory");
    }
}

// ------------------------- LayerNorm stats + apply ------------------------
__global__ void stats_kernel()
{
    int b = threadIdx.x;
    if (b >= BATCH) return;
    double s = 0.0, ss = 0.0;
    for (int bm = b * 16; bm < b * 16 + 16; ++bm)
        for (int bn = 0; bn < 2; ++bn) {
            int pid = bm * 2 + bn;
            s  += (double)g_psum[2 * pid];
            ss += (double)g_psum[2 * pid + 1];
        }
    const double nd = (double)LSEQ * NOUT;
    double mu = s / nd;
    double var = ss / nd - mu * mu;
    g_stats[b] = make_float2((float)mu, (float)rsqrt(var + 1e-5));
}

__global__ void __launch_bounds__(256)
norm_kernel(float* __restrict__ out, const float* __restrict__ lnw,
            const float* __restrict__ lnb)
{
    size_t i4 = (size_t)blockIdx.x * 256 + threadIdx.x;
    size_t base = i4 * 4;
    int row = (int)(base >> 8);
    int b = row >> 11;
    int l = row & 2047;
    int o = (int)(base & 255);
    float2 st = g_stats[b];
    float4 v = *(float4*)(out + base);
    const float4 w  = *(const float4*)(lnw + (size_t)l * 256 + o);
    const float4 bb = *(const float4*)(lnb + (size_t)l * 256 + o);
    v.x = (v.x - st.x) * st.y * w.x + bb.x;
    v.y = (v.y - st.x) * st.y * w.y + bb.y;
    v.z = (v.z - st.x) * st.y * w.z + bb.z;
    v.w = (v.w - st.x) * st.y * w.w + bb.w;
    *(float4*)(out + base) = v;
}

// ------------------------------- launch -----------------------------------
extern "C" void kernel_launch(void* const* d_in, const int* in_sizes, int n_in,
                              void* d_out, int out_size)
{
    const float* inputs    = (const float*)d_in[0];
    const float* in_proj_w = (const float*)d_in[1];
    const float* conv_w    = (const float*)d_in[2];
    const float* conv_b    = (const float*)d_in[3];
    const float* x_proj_w  = (const float*)d_in[4];
    const float* dt_proj_w = (const float*)d_in[5];
    const float* dt_proj_b = (const float*)d_in[6];
    const float* A_log     = (const float*)d_in[7];
    const float* D_skip    = (const float*)d_in[8];
    const float* out_proj_w= (const float*)d_in[9];
    const float* dim_w     = (const float*)d_in[10];
    const float* dim_b     = (const float*)d_in[11];
    const float* ln_w      = (const float*)d_in[12];
    const float* ln_b      = (const float*)d_in[13];
    float* out = (float*)d_out;

    float *xz, *y, *t1;
    cudaGetSymbolAddress((void**)&xz, g_xz);
    cudaGetSymbolAddress((void**)&y,  g_y);
    cudaGetSymbolAddress((void**)&t1, g_t1);

    cudaFuncSetAttribute(gemm_bf16_kernel<1>,
                         cudaFuncAttributeMaxDynamicSharedMemorySize, GSM_BYTES);
    cudaFuncSetAttribute(gemm_bf16_kernel<2>,
                         cudaFuncAttributeMaxDynamicSharedMemorySize, GSM_BYTES);
    cudaFuncSetAttribute(gemm_bf16_kernel<3>,
                         cudaFuncAttributeMaxDynamicSharedMemorySize, GSM_BYTES);

    // 1) xz = inputs @ in_proj_w^T  [32768 x 1024], silu on z half (bn>=4)
    gemm_bf16_kernel<3><<<dim3(1024 / 128, NROWS / 128), 256, GSM_BYTES>>>(
        inputs, in_proj_w, xz, 1024, 256, nullptr);

    // 2) conv + silu + x_proj + dt_proj, packed scan inputs
    convproj_kernel<<<NROWS / TOK, 512>>>(conv_w, conv_b, x_proj_w,
                                          dt_proj_w, dt_proj_b, D_skip);

    // 3) selective scan (v5: cp.async depth-4 pipeline)
    scan_kernel<<<512, 128>>>(A_log);

    // 4) t1 = silu(y @ out_proj_w^T)  [32768 x 256]
    gemm_bf16_kernel<1><<<dim3(256 / 128, NROWS / 128), 256, GSM_BYTES>>>(
        y, out_proj_w, t1, 256, 512, nullptr);

    // 5) out = t1 @ dim_w^T + dim_b, + per-block partial sums
    gemm_bf16_kernel<2><<<dim3(256 / 128, NROWS / 128), 256, GSM_BYTES>>>(
        t1, dim_w, out, 256, 256, dim_b);

    // 6) per-batch LayerNorm
    stats_kernel<<<1, 32>>>();
    norm_kernel<<<(NROWS * NOUT / 4) / 256, 256>>>(out, ln_w, ln_b);
}